// round 6
// baseline (speedup 1.0000x reference)
#include <cuda_runtime.h>
#include <cuda_bf16.h>
#include <mma.h>

using namespace nvcuda;

#define Bb 256
#define Dd 256
#define Tt 512
#define Hh 512
#define G4 2048
#define Mm (Tt*Bb)   // 131072

// ---------------- device scratch (no runtime allocation allowed) ----------------
__device__ __nv_bfloat16 g_xb[(size_t)Mm*Dd];        // xs as bf16, [t*B+b][d]
__device__ float         g_xg[(size_t)Mm*G4];        // x_gates fp32 (includes biases)
__device__ __nv_bfloat16 g_wih[(size_t)Dd*G4];       // W_ih^T bf16 [k][n]
__device__ __nv_bfloat16 g_whh[(size_t)Hh*G4];       // W_hh^T bf16 [k][n]
__device__ float         g_biasmat[16*G4];           // 16 identical rows of (b_ih+b_hh)
__device__ __nv_bfloat16 g_h[2][(size_t)Bb*Hh];      // double-buffered hidden state
__device__ float         g_plog[16*(size_t)Tt*Bb];   // partial logits per u-tile
__device__ unsigned int  g_ctr[16][32];              // per 16-batch-group counter (128B apart)

__device__ __forceinline__ float tanh_fast(float x) {
    float y; asm("tanh.approx.f32 %0, %1;" : "=f"(y) : "f"(x)); return y;
}
__device__ __forceinline__ float sigm(float x) { return 1.0f / (1.0f + __expf(-x)); }

__device__ __forceinline__ void cp16(void* dst, const void* src) {
    unsigned d = (unsigned)__cvta_generic_to_shared(dst);
    asm volatile("cp.async.cg.shared.global [%0], [%1], 16;" :: "r"(d), "l"(src));
}

// ---------------- init: zero h0 and counters ----------------
__global__ void k_init() {
    int i = blockIdx.x * blockDim.x + threadIdx.x;
    if (i < 16 * 32) ((unsigned*)g_ctr)[i] = 0u;
    if (i < Bb * Hh) g_h[0][i] = __float2bfloat16(0.0f);
}

// ---------------- weight converts (transpose to [k][n], bf16) ----------------
__global__ void k_convert(const float* __restrict__ Wih, const float* __restrict__ Whh,
                          const float* __restrict__ bih, const float* __restrict__ bhh) {
    int i = blockIdx.x * blockDim.x + threadIdx.x;
    if (i < Dd * G4) {
        int k = i / G4, n = i % G4;
        g_wih[i] = __float2bfloat16(Wih[(size_t)n * Dd + k]);
    }
    if (i < Hh * G4) {
        int k = i / G4, n = i % G4;
        g_whh[i] = __float2bfloat16(Whh[(size_t)n * Hh + k]);
    }
    if (i < 16 * G4) {
        int n = i % G4;
        g_biasmat[i] = bih[n] + bhh[n];
    }
}

// ---------------- transpose x (B,D,T) -> g_xb[(t*B+b)*D + d] bf16 ----------------
__global__ void k_transpose(const float* __restrict__ x) {
    __shared__ float tile[32][33];
    int b  = blockIdx.z;
    int d0 = blockIdx.y * 32, t0 = blockIdx.x * 32;
    int tx = threadIdx.x, ty = threadIdx.y;   // 32 x 8
    const float* src = x + ((size_t)b * Dd + d0) * Tt + t0;
    for (int r = ty; r < 32; r += 8)
        tile[r][tx] = src[(size_t)r * Tt + tx];
    __syncthreads();
    for (int r = ty; r < 32; r += 8)
        g_xb[((size_t)(t0 + r) * Bb + b) * Dd + d0 + tx] = __float2bfloat16(tile[tx][r]);
}

// ---------------- GEMM1: g_xg = g_xb (M x 256) @ g_wih (256 x 2048) + bias ----------------
#define GA_LD 72
#define GB_LD 136
#define G1_SMEM (2*128*GA_LD*2 + 2*64*GB_LD*2)

__global__ void __launch_bounds__(256, 2) k_gemm1() {
    extern __shared__ char smg[];
    __nv_bfloat16 (*As)[128][GA_LD] = (__nv_bfloat16(*)[128][GA_LD])smg;
    __nv_bfloat16 (*Bs)[64][GB_LD]  = (__nv_bfloat16(*)[64][GB_LD])(smg + 2*128*GA_LD*2);

    int n0 = blockIdx.x * 128, m0 = blockIdx.y * 128;   // n fastest -> A-tile reuse in L2
    int tid = threadIdx.x;
    int w = tid >> 5;
    int mw = (w >> 1) * 32, nw = (w & 1) * 64;

    auto load_stage = [&](int c, int s) {
        int k0 = c * 64;
        #pragma unroll
        for (int p = 0; p < 4; p++) {
            int idx = tid + p * 256;
            int r = idx >> 3, cc = (idx & 7) * 8;
            cp16(&As[s][r][cc], &g_xb[(size_t)(m0 + r) * Dd + k0 + cc]);
        }
        #pragma unroll
        for (int p = 0; p < 4; p++) {
            int idx = tid + p * 256;
            int r = idx >> 4, cc = (idx & 15) * 8;
            cp16(&Bs[s][r][cc], &g_wih[(size_t)(k0 + r) * G4 + n0 + cc]);
        }
        asm volatile("cp.async.commit_group;" ::: "memory");
    };

    load_stage(0, 0);

    wmma::fragment<wmma::accumulator, 16, 16, 16, float> acc[2][4];
    #pragma unroll
    for (int i = 0; i < 2; i++)
        #pragma unroll
        for (int j = 0; j < 4; j++)
            wmma::load_matrix_sync(acc[i][j], &g_biasmat[n0 + nw + 16 * j], G4, wmma::mem_row_major);

    #pragma unroll
    for (int c = 0; c < 4; c++) {
        if (c < 3) load_stage(c + 1, (c + 1) & 1);
        if (c < 3) asm volatile("cp.async.wait_group 1;" ::: "memory");
        else       asm volatile("cp.async.wait_group 0;" ::: "memory");
        __syncthreads();
        int s = c & 1;
        #pragma unroll
        for (int kk = 0; kk < 64; kk += 16) {
            wmma::fragment<wmma::matrix_a, 16, 16, 16, __nv_bfloat16, wmma::row_major> af[2];
            wmma::fragment<wmma::matrix_b, 16, 16, 16, __nv_bfloat16, wmma::row_major> bf[4];
            #pragma unroll
            for (int i = 0; i < 2; i++)
                wmma::load_matrix_sync(af[i], &As[s][mw + 16 * i][kk], GA_LD);
            #pragma unroll
            for (int j = 0; j < 4; j++)
                wmma::load_matrix_sync(bf[j], &Bs[s][kk][nw + 16 * j], GB_LD);
            #pragma unroll
            for (int i = 0; i < 2; i++)
                #pragma unroll
                for (int j = 0; j < 4; j++)
                    wmma::mma_sync(acc[i][j], af[i], bf[j], acc[i][j]);
        }
        __syncthreads();
    }
    #pragma unroll
    for (int i = 0; i < 2; i++)
        #pragma unroll
        for (int j = 0; j < 4; j++)
            wmma::store_matrix_sync(&g_xg[(size_t)(m0 + mw + 16 * i) * G4 + n0 + nw + 16 * j],
                                    acc[i][j], G4, wmma::mem_row_major);
}

// ---------------- persistent LSTM recurrence: DUAL-PIPELINE ----------------
// 128 CTAs: blockIdx = p*16 + ut, p in 0..7 (pair), ut in 0..15 (unit tile of 32).
// CTA runs TWO independent 16-batch groups: A = rows [p*32, +16), B = rows [p*32+16, +16).
// While one group's barrier/latency settles, the CTA computes the other group.
#define BS_LD 136
#define AS_LD 520
#define GT_LD 132
#define DSMEM_BYTES (512*BS_LD*2 + 2*16*AS_LD*2 + 2*16*GT_LD*4)

__global__ void __launch_bounds__(256, 1) k_lstm(const float* __restrict__ Wmlp) {
    extern __shared__ char smem[];
    __nv_bfloat16* Bs  = (__nv_bfloat16*)smem;                                   // [512][BS_LD]
    __nv_bfloat16* AsA = (__nv_bfloat16*)(smem + 512 * BS_LD * 2);               // [16][AS_LD]
    __nv_bfloat16* AsB = AsA + 16 * AS_LD;
    float*         GtA = (float*)(smem + 512 * BS_LD * 2 + 2 * 16 * AS_LD * 2);  // [16][GT_LD]
    float*         GtB = GtA + 16 * GT_LD;
    __shared__ float Wm[32];

    int tid = threadIdx.x, w = tid >> 5;
    int ut = blockIdx.x & 15, p = blockIdx.x >> 4;
    int u0 = ut * 32;
    int bA0 = p * 32, bB0 = p * 32 + 16;
    unsigned* ctrA = &g_ctr[2 * p][0];
    unsigned* ctrB = &g_ctr[2 * p + 1][0];
    int wc = w * 16;              // warp's 16 gate-columns (gate w>>1, half w&1)

    // preload W_hh slice: Bs[k][g*32+uu] = W_hh[g*512+u0+uu][k]
    for (int idx = tid; idx < 512 * 16; idx += 256) {
        int k = idx >> 4;
        int col = (idx & 15) * 8;
        int g = col >> 5, uu = col & 31;
        *(uint4*)&Bs[k * BS_LD + col] = *(const uint4*)&g_whh[(size_t)k * G4 + g * 512 + u0 + uu];
    }
    if (tid < 32) Wm[tid] = Wmlp[u0 + tid];

    // elementwise ownership: batch row eb = tid>>4 (0..15), unit pair eq = tid&15 (units eq*2, eq*2+1)
    int eb = tid >> 4, eq = tid & 15;

    float cA[2] = {0.0f, 0.0f}, cB[2] = {0.0f, 0.0f};
    float2 xrA[4], xrB[4];
    {
        const float* xa = g_xg + ((size_t)0 * Bb + bA0 + eb) * G4 + u0 + eq * 2;
        const float* xb = g_xg + ((size_t)0 * Bb + bB0 + eb) * G4 + u0 + eq * 2;
        #pragma unroll
        for (int g = 0; g < 4; g++) {
            xrA[g] = __ldg((const float2*)(xa + g * 512));
            xrB[g] = __ldg((const float2*)(xb + g * 512));
        }
    }

    __syncthreads();

    for (int t = 0; t < Tt; t++) {
        int cur = t & 1, nxt = cur ^ 1;

        // ================= group A =================
        {
            const __nv_bfloat16* hsrc = g_h[cur] + (size_t)bA0 * Hh;
            #pragma unroll
            for (int it = 0; it < 4; it++) {
                int idx = tid + it * 256;
                int r = idx >> 6, c = (idx & 63) * 8;
                *(uint4*)&AsA[r * AS_LD + c] = __ldcg((const uint4*)&hsrc[(size_t)r * Hh + c]);
            }
            __syncthreads();

            wmma::fragment<wmma::accumulator, 16, 16, 16, float> acc;
            wmma::fill_fragment(acc, 0.0f);
            #pragma unroll 8
            for (int k0 = 0; k0 < 512; k0 += 16) {
                wmma::fragment<wmma::matrix_a, 16, 16, 16, __nv_bfloat16, wmma::row_major> af;
                wmma::fragment<wmma::matrix_b, 16, 16, 16, __nv_bfloat16, wmma::row_major> bf;
                wmma::load_matrix_sync(af, &AsA[k0], AS_LD);
                wmma::load_matrix_sync(bf, &Bs[k0 * BS_LD + wc], BS_LD);
                wmma::mma_sync(acc, af, bf, acc);
            }
            wmma::store_matrix_sync(&GtA[wc], acc, GT_LD, wmma::mem_row_major);
            __syncthreads();

            const float* grow = &GtA[eb * GT_LD + eq * 2];
            float xv[4][2] = {{xrA[0].x, xrA[0].y}, {xrA[1].x, xrA[1].y},
                              {xrA[2].x, xrA[2].y}, {xrA[3].x, xrA[3].y}};
            __nv_bfloat16 tmp[2];
            float s = 0.0f;
            #pragma unroll
            for (int e = 0; e < 2; e++) {
                float gi = grow[0 * 32 + e] + xv[0][e];
                float gf = grow[1 * 32 + e] + xv[1][e];
                float gg = grow[2 * 32 + e] + xv[2][e];
                float go = grow[3 * 32 + e] + xv[3][e];
                float ig = sigm(gi), fg = sigm(gf), gv = tanh_fast(gg), og = sigm(go);
                float cn = fg * cA[e] + ig * gv;
                cA[e] = cn;
                float hv = og * tanh_fast(cn);
                tmp[e] = __float2bfloat16(hv);
                s += hv * Wm[eq * 2 + e];
            }
            __stcg((unsigned*)&g_h[nxt][(size_t)(bA0 + eb) * Hh + u0 + eq * 2], *(unsigned*)tmp);
            s += __shfl_down_sync(0xffffffffu, s, 8, 16);
            s += __shfl_down_sync(0xffffffffu, s, 4, 16);
            s += __shfl_down_sync(0xffffffffu, s, 2, 16);
            s += __shfl_down_sync(0xffffffffu, s, 1, 16);
            if (eq == 0) g_plog[((size_t)ut * Tt + t) * Bb + bA0 + eb] = s;

            if (t + 1 < Tt) {
                const float* xa = g_xg + ((size_t)(t + 1) * Bb + bA0 + eb) * G4 + u0 + eq * 2;
                #pragma unroll
                for (int g = 0; g < 4; g++)
                    xrA[g] = __ldg((const float2*)(xa + g * 512));
            }
        }

        // arrive A(t); poll B for step t readiness (B's step-(t-1) arrivals; other-phase time has passed)
        __syncthreads();
        if (tid == 0) {
            asm volatile("red.release.gpu.global.add.u32 [%0], 1;" :: "l"(ctrA) : "memory");
            if (t > 0) {
                unsigned tgt = 16u * (unsigned)t, v;
                do {
                    asm volatile("ld.acquire.gpu.global.u32 %0, [%1];" : "=r"(v) : "l"(ctrB) : "memory");
                } while (v < tgt);
            }
        }
        __syncthreads();

        // ================= group B =================
        {
            const __nv_bfloat16* hsrc = g_h[cur] + (size_t)bB0 * Hh;
            #pragma unroll
            for (int it = 0; it < 4; it++) {
                int idx = tid + it * 256;
                int r = idx >> 6, c = (idx & 63) * 8;
                *(uint4*)&AsB[r * AS_LD + c] = __ldcg((const uint4*)&hsrc[(size_t)r * Hh + c]);
            }
            __syncthreads();

            wmma::fragment<wmma::accumulator, 16, 16, 16, float> acc;
            wmma::fill_fragment(acc, 0.0f);
            #pragma unroll 8
            for (int k0 = 0; k0 < 512; k0 += 16) {
                wmma::fragment<wmma::matrix_a, 16, 16, 16, __nv_bfloat16, wmma::row_major> af;
                wmma::fragment<wmma::matrix_b, 16, 16, 16, __nv_bfloat16, wmma::row_major> bf;
                wmma::load_matrix_sync(af, &AsB[k0], AS_LD);
                wmma::load_matrix_sync(bf, &Bs[k0 * BS_LD + wc], BS_LD);
                wmma::mma_sync(acc, af, bf, acc);
            }
            wmma::store_matrix_sync(&GtB[wc], acc, GT_LD, wmma::mem_row_major);
            __syncthreads();

            const float* grow = &GtB[eb * GT_LD + eq * 2];
            float xv[4][2] = {{xrB[0].x, xrB[0].y}, {xrB[1].x, xrB[1].y},
                              {xrB[2].x, xrB[2].y}, {xrB[3].x, xrB[3].y}};
            __nv_bfloat16 tmp[2];
            float s = 0.0f;
            #pragma unroll
            for (int e = 0; e < 2; e++) {
                float gi = grow[0 * 32 + e] + xv[0][e];
                float gf = grow[1 * 32 + e] + xv[1][e];
                float gg = grow[2 * 32 + e] + xv[2][e];
                float go = grow[3 * 32 + e] + xv[3][e];
                float ig = sigm(gi), fg = sigm(gf), gv = tanh_fast(gg), og = sigm(go);
                float cn = fg * cB[e] + ig * gv;
                cB[e] = cn;
                float hv = og * tanh_fast(cn);
                tmp[e] = __float2bfloat16(hv);
                s += hv * Wm[eq * 2 + e];
            }
            __stcg((unsigned*)&g_h[nxt][(size_t)(bB0 + eb) * Hh + u0 + eq * 2], *(unsigned*)tmp);
            s += __shfl_down_sync(0xffffffffu, s, 8, 16);
            s += __shfl_down_sync(0xffffffffu, s, 4, 16);
            s += __shfl_down_sync(0xffffffffu, s, 2, 16);
            s += __shfl_down_sync(0xffffffffu, s, 1, 16);
            if (eq == 0) g_plog[((size_t)ut * Tt + t) * Bb + bB0 + eb] = s;

            if (t + 1 < Tt) {
                const float* xb = g_xg + ((size_t)(t + 1) * Bb + bB0 + eb) * G4 + u0 + eq * 2;
                #pragma unroll
                for (int g = 0; g < 4; g++)
                    xrB[g] = __ldg((const float2*)(xb + g * 512));
            }
        }

        // arrive B(t); poll A for step t+1 readiness (A's arrivals through step t)
        __syncthreads();
        if (tid == 0) {
            asm volatile("red.release.gpu.global.add.u32 [%0], 1;" :: "l"(ctrB) : "memory");
            if (t + 1 < Tt) {
                unsigned tgt = 16u * (unsigned)(t + 1), v;
                do {
                    asm volatile("ld.acquire.gpu.global.u32 %0, [%1];" : "=r"(v) : "l"(ctrA) : "memory");
                } while (v < tgt);
            }
        }
        __syncthreads();
    }
}

// ---------------- reduce partial logits -> sigmoid -> out (B, T) ----------------
__global__ void k_out(const float* __restrict__ bmlp, float* __restrict__ out) {
    int t = blockIdx.x, b = threadIdx.x;
    float s = bmlp[0];
    #pragma unroll
    for (int j = 0; j < 16; j++)
        s += g_plog[((size_t)j * Tt + t) * Bb + b];
    out[(size_t)b * Tt + t] = 1.0f / (1.0f + __expf(-s));
}

// ---------------- launch ----------------
extern "C" void kernel_launch(void* const* d_in, const int* in_sizes, int n_in,
                              void* d_out, int out_size) {
    const float* x    = (const float*)d_in[0];
    const float* Wih  = (const float*)d_in[1];
    const float* Whh  = (const float*)d_in[2];
    const float* bih  = (const float*)d_in[3];
    const float* bhh  = (const float*)d_in[4];
    const float* Wmlp = (const float*)d_in[5];
    const float* bmlp = (const float*)d_in[6];
    float* out = (float*)d_out;

    k_init<<<512, 256>>>();
    k_convert<<<4096, 256>>>(Wih, Whh, bih, bhh);
    k_transpose<<<dim3(Tt / 32, Dd / 32, Bb), dim3(32, 8)>>>(x);

    cudaFuncSetAttribute(k_gemm1, cudaFuncAttributeMaxDynamicSharedMemorySize, G1_SMEM);
    k_gemm1<<<dim3(G4 / 128, Mm / 128), 256, G1_SMEM>>>();   // n fastest

    cudaFuncSetAttribute(k_lstm, cudaFuncAttributeMaxDynamicSharedMemorySize, DSMEM_BYTES);
    k_lstm<<<128, 256, DSMEM_BYTES>>>(Wmlp);

    k_out<<<Tt, Bb>>>(bmlp, out);
}

// round 9
// speedup vs baseline: 1.1469x; 1.1469x over previous
#include <cuda_runtime.h>
#include <cuda_bf16.h>
#include <mma.h>

using namespace nvcuda;

#define Bb 256
#define Dd 256
#define Tt 512
#define Hh 512
#define G4 2048
#define Mm (Tt*Bb)   // 131072

// ---------------- device scratch (no runtime allocation allowed) ----------------
__device__ __nv_bfloat16 g_xb[(size_t)Mm*Dd];        // xs as bf16, [t*B+b][d]
__device__ float         g_xg[(size_t)Mm*G4];        // x_gates fp32 (includes biases)
__device__ __nv_bfloat16 g_wih[(size_t)Dd*G4];       // W_ih^T bf16 [k][n]
__device__ __nv_bfloat16 g_whh[(size_t)Hh*G4];       // W_hh^T bf16 [k][n]
__device__ float         g_biasmat[16*G4];           // 16 identical rows of (b_ih+b_hh)
__device__ __nv_bfloat16 g_h[2][(size_t)Bb*Hh];      // double-buffered hidden state
__device__ float         g_plog[16*(size_t)Tt*Bb];   // partial logits per u-tile
__device__ unsigned int  g_ctr[8][32];               // per batch-group counter (128B apart)

__device__ __forceinline__ float tanh_fast(float x) {
    float y; asm("tanh.approx.f32 %0, %1;" : "=f"(y) : "f"(x)); return y;
}
__device__ __forceinline__ float sigm(float x) { return 1.0f / (1.0f + __expf(-x)); }

__device__ __forceinline__ void cp16(void* dst, const void* src) {
    unsigned d = (unsigned)__cvta_generic_to_shared(dst);
    asm volatile("cp.async.cg.shared.global [%0], [%1], 16;" :: "r"(d), "l"(src));
}

// ---------------- init: zero h0 and counters ----------------
__global__ void k_init() {
    int i = blockIdx.x * blockDim.x + threadIdx.x;
    if (i < 8 * 32) ((unsigned*)g_ctr)[i] = 0u;
    if (i < Bb * Hh) g_h[0][i] = __float2bfloat16(0.0f);
}

// ---------------- weight converts (transpose to [k][n], bf16) ----------------
__global__ void k_convert(const float* __restrict__ Wih, const float* __restrict__ Whh,
                          const float* __restrict__ bih, const float* __restrict__ bhh) {
    int i = blockIdx.x * blockDim.x + threadIdx.x;
    if (i < Dd * G4) {
        int k = i / G4, n = i % G4;
        g_wih[i] = __float2bfloat16(Wih[(size_t)n * Dd + k]);
    }
    if (i < Hh * G4) {
        int k = i / G4, n = i % G4;
        g_whh[i] = __float2bfloat16(Whh[(size_t)n * Hh + k]);
    }
    if (i < 16 * G4) {
        int n = i % G4;
        g_biasmat[i] = bih[n] + bhh[n];
    }
}

// ---------------- transpose x (B,D,T) -> g_xb[(t*B+b)*D + d] bf16 ----------------
__global__ void k_transpose(const float* __restrict__ x) {
    __shared__ float tile[32][33];
    int b  = blockIdx.z;
    int d0 = blockIdx.y * 32, t0 = blockIdx.x * 32;
    int tx = threadIdx.x, ty = threadIdx.y;   // 32 x 8
    const float* src = x + ((size_t)b * Dd + d0) * Tt + t0;
    for (int r = ty; r < 32; r += 8)
        tile[r][tx] = src[(size_t)r * Tt + tx];
    __syncthreads();
    for (int r = ty; r < 32; r += 8)
        g_xb[((size_t)(t0 + r) * Bb + b) * Dd + d0 + tx] = __float2bfloat16(tile[tx][r]);
}

// ---------------- GEMM1: g_xg = g_xb (M x 256) @ g_wih (256 x 2048) + bias ----------------
#define GA_LD 72
#define GB_LD 136
#define G1_SMEM (2*128*GA_LD*2 + 2*64*GB_LD*2)

__global__ void __launch_bounds__(256, 2) k_gemm1() {
    extern __shared__ char smg[];
    __nv_bfloat16 (*As)[128][GA_LD] = (__nv_bfloat16(*)[128][GA_LD])smg;
    __nv_bfloat16 (*Bs)[64][GB_LD]  = (__nv_bfloat16(*)[64][GB_LD])(smg + 2*128*GA_LD*2);

    int n0 = blockIdx.x * 128, m0 = blockIdx.y * 128;   // n fastest -> A-tile reuse in L2
    int tid = threadIdx.x;
    int w = tid >> 5;
    int mw = (w >> 1) * 32, nw = (w & 1) * 64;

    auto load_stage = [&](int c, int s) {
        int k0 = c * 64;
        #pragma unroll
        for (int p = 0; p < 4; p++) {
            int idx = tid + p * 256;
            int r = idx >> 3, cc = (idx & 7) * 8;
            cp16(&As[s][r][cc], &g_xb[(size_t)(m0 + r) * Dd + k0 + cc]);
        }
        #pragma unroll
        for (int p = 0; p < 4; p++) {
            int idx = tid + p * 256;
            int r = idx >> 4, cc = (idx & 15) * 8;
            cp16(&Bs[s][r][cc], &g_wih[(size_t)(k0 + r) * G4 + n0 + cc]);
        }
        asm volatile("cp.async.commit_group;" ::: "memory");
    };

    load_stage(0, 0);

    wmma::fragment<wmma::accumulator, 16, 16, 16, float> acc[2][4];
    #pragma unroll
    for (int i = 0; i < 2; i++)
        #pragma unroll
        for (int j = 0; j < 4; j++)
            wmma::load_matrix_sync(acc[i][j], &g_biasmat[n0 + nw + 16 * j], G4, wmma::mem_row_major);

    #pragma unroll
    for (int c = 0; c < 4; c++) {
        if (c < 3) load_stage(c + 1, (c + 1) & 1);
        if (c < 3) asm volatile("cp.async.wait_group 1;" ::: "memory");
        else       asm volatile("cp.async.wait_group 0;" ::: "memory");
        __syncthreads();
        int s = c & 1;
        #pragma unroll
        for (int kk = 0; kk < 64; kk += 16) {
            wmma::fragment<wmma::matrix_a, 16, 16, 16, __nv_bfloat16, wmma::row_major> af[2];
            wmma::fragment<wmma::matrix_b, 16, 16, 16, __nv_bfloat16, wmma::row_major> bf[4];
            #pragma unroll
            for (int i = 0; i < 2; i++)
                wmma::load_matrix_sync(af[i], &As[s][mw + 16 * i][kk], GA_LD);
            #pragma unroll
            for (int j = 0; j < 4; j++)
                wmma::load_matrix_sync(bf[j], &Bs[s][kk][nw + 16 * j], GB_LD);
            #pragma unroll
            for (int i = 0; i < 2; i++)
                #pragma unroll
                for (int j = 0; j < 4; j++)
                    wmma::mma_sync(acc[i][j], af[i], bf[j], acc[i][j]);
        }
        __syncthreads();
    }
    #pragma unroll
    for (int i = 0; i < 2; i++)
        #pragma unroll
        for (int j = 0; j < 4; j++)
            wmma::store_matrix_sync(&g_xg[(size_t)(m0 + mw + 16 * i) * G4 + n0 + nw + 16 * j],
                                    acc[i][j], G4, wmma::mem_row_major);
}

// ---------------- persistent LSTM recurrence ----------------
// grid = 128 CTAs: blockIdx = bt*16 + ut ; CTA owns batch rows [bt*32,+32), units [ut*32,+32)
// 8 warps: warp w -> batch half (w&1), gate (w>>1). Split-K: 4 independent HMMA chains/warp.
#define BS_LD 136
#define AS_LD 520
#define GT_LD 132
#define DSMEM_BYTES (512*BS_LD*2 + 32*AS_LD*2 + 32*GT_LD*4)

__global__ void __launch_bounds__(256, 1) k_lstm(const float* __restrict__ Wmlp) {
    extern __shared__ char smem[];
    __nv_bfloat16* Bs = (__nv_bfloat16*)smem;                          // [512][BS_LD]
    __nv_bfloat16* As = (__nv_bfloat16*)(smem + 512 * BS_LD * 2);      // [32][AS_LD]
    float*         Gt = (float*)(smem + 512 * BS_LD * 2 + 32 * AS_LD * 2); // [32][GT_LD]
    __shared__ float Wm[32];

    int tid = threadIdx.x, w = tid >> 5;
    int ut = blockIdx.x & 15, bt = blockIdx.x >> 4;
    int u0 = ut * 32, b0 = bt * 32;
    int bh = (w & 1) * 16;        // batch half
    int cg = w >> 1;              // gate index 0..3 (32 gate-cols)
    unsigned* ctr = &g_ctr[bt][0];

    // preload W_hh slice into SMEM: Bs[k][g*32+uu] = W_hh[g*512+u0+uu][k]
    for (int idx = tid; idx < 512 * 16; idx += 256) {
        int k = idx >> 4;
        int col = (idx & 15) * 8;
        int g = col >> 5, uu = col & 31;
        *(uint4*)&Bs[k * BS_LD + col] = *(const uint4*)&g_whh[(size_t)k * G4 + g * 512 + u0 + uu];
    }
    if (tid < 32) Wm[tid] = Wmlp[u0 + tid];

    // elementwise ownership: batch row eb = tid>>3 (0..31), unit quad eq = tid&7 (4 units each)
    int eb = tid >> 3, eq = tid & 7;

    float c_reg[4];
    #pragma unroll
    for (int e = 0; e < 4; e++) c_reg[e] = 0.0f;

    // prefetch xg for t=0 into registers (4 gates x 4 floats)
    float4 xr[4];
    {
        const float* xbase = g_xg + ((size_t)0 * Bb + b0 + eb) * G4 + u0 + eq * 4;
        #pragma unroll
        for (int g = 0; g < 4; g++)
            xr[g] = __ldg((const float4*)(xbase + g * 512));
    }

    __syncthreads();

    for (int t = 0; t < Tt; t++) {
        int cur = t & 1, nxt = cur ^ 1;

        // copy my h rows (32 x 512 bf16) from global (L2-coherent) into SMEM
        const __nv_bfloat16* hsrc = g_h[cur] + (size_t)b0 * Hh;
        #pragma unroll
        for (int it = 0; it < 8; it++) {
            int idx = tid + it * 256;
            int r = idx >> 6, c = (idx & 63) * 8;
            *(uint4*)&As[r * AS_LD + c] = __ldcg((const uint4*)&hsrc[(size_t)r * Hh + c]);
        }
        __syncthreads();

        // raw recurrent gate sums: 4 independent HMMA chains per warp (2 cols x 2 k-parity)
        wmma::fragment<wmma::accumulator, 16, 16, 16, float> acc[2][2];
        #pragma unroll
        for (int j = 0; j < 2; j++)
            #pragma unroll
            for (int p = 0; p < 2; p++)
                wmma::fill_fragment(acc[j][p], 0.0f);

        #pragma unroll 4
        for (int k0 = 0; k0 < 512; k0 += 32) {
            wmma::fragment<wmma::matrix_a, 16, 16, 16, __nv_bfloat16, wmma::row_major> af[2];
            #pragma unroll
            for (int p = 0; p < 2; p++)
                wmma::load_matrix_sync(af[p], &As[bh * AS_LD + k0 + p * 16], AS_LD);
            #pragma unroll
            for (int j = 0; j < 2; j++) {
                #pragma unroll
                for (int p = 0; p < 2; p++) {
                    wmma::fragment<wmma::matrix_b, 16, 16, 16, __nv_bfloat16, wmma::row_major> bf;
                    wmma::load_matrix_sync(bf, &Bs[(k0 + p * 16) * BS_LD + cg * 32 + 16 * j], BS_LD);
                    wmma::mma_sync(acc[j][p], af[p], bf, acc[j][p]);
                }
            }
        }

        // combine k-parity chains (identical fragment layouts) and store
        #pragma unroll
        for (int j = 0; j < 2; j++) {
            #pragma unroll
            for (int e = 0; e < acc[j][0].num_elements; e++)
                acc[j][0].x[e] += acc[j][1].x[e];
            wmma::store_matrix_sync(&Gt[bh * GT_LD + cg * 32 + 16 * j], acc[j][0], GT_LD, wmma::mem_row_major);
        }
        __syncthreads();

        // elementwise cell: gates = Gt + xr (prefetched); write h + partial logit
        {
            const float* grow = &Gt[eb * GT_LD + eq * 4];
            const float* xf = (const float*)xr;
            __nv_bfloat16 tmp[4];
            float s = 0.0f;
            #pragma unroll
            for (int e = 0; e < 4; e++) {
                float gi = grow[0 * 32 + e] + xf[0 * 4 + e];
                float gf = grow[1 * 32 + e] + xf[1 * 4 + e];
                float gg = grow[2 * 32 + e] + xf[2 * 4 + e];
                float go = grow[3 * 32 + e] + xf[3 * 4 + e];
                float ig = sigm(gi);
                float fg = sigm(gf);
                float gv = tanh_fast(gg);
                float og = sigm(go);
                float cn = fg * c_reg[e] + ig * gv;
                c_reg[e] = cn;
                float hv = og * tanh_fast(cn);
                tmp[e] = __float2bfloat16(hv);
                s += hv * Wm[eq * 4 + e];
            }
            __stcg((uint2*)&g_h[nxt][(size_t)(b0 + eb) * Hh + u0 + eq * 4], *(uint2*)tmp);
            s += __shfl_down_sync(0xffffffffu, s, 4, 8);
            s += __shfl_down_sync(0xffffffffu, s, 2, 8);
            s += __shfl_down_sync(0xffffffffu, s, 1, 8);
            if (eq == 0) g_plog[((size_t)ut * Tt + t) * Bb + b0 + eb] = s;
        }

        // prefetch xg for t+1 (in flight across the barrier wait)
        if (t + 1 < Tt) {
            const float* xbase = g_xg + ((size_t)(t + 1) * Bb + b0 + eb) * G4 + u0 + eq * 4;
            #pragma unroll
            for (int g = 0; g < 4; g++)
                xr[g] = __ldg((const float4*)(xbase + g * 512));
        }

        // group barrier: 16 CTAs of this batch group (skip after last step)
        if (t + 1 < Tt) {
            __syncthreads();
            if (tid == 0) {
                asm volatile("red.release.gpu.global.add.u32 [%0], 1;" :: "l"(ctr) : "memory");
                unsigned tgt = 16u * (unsigned)(t + 1);
                unsigned v;
                do {
                    asm volatile("ld.acquire.gpu.global.u32 %0, [%1];" : "=r"(v) : "l"(ctr) : "memory");
                } while (v < tgt);
            }
            __syncthreads();
        }
    }
}

// ---------------- reduce partial logits -> sigmoid -> out (B, T) ----------------
__global__ void k_out(const float* __restrict__ bmlp, float* __restrict__ out) {
    int t = blockIdx.x, b = threadIdx.x;
    float s = bmlp[0];
    #pragma unroll
    for (int j = 0; j < 16; j++)
        s += g_plog[((size_t)j * Tt + t) * Bb + b];
    out[(size_t)b * Tt + t] = 1.0f / (1.0f + __expf(-s));
}

// ---------------- launch ----------------
extern "C" void kernel_launch(void* const* d_in, const int* in_sizes, int n_in,
                              void* d_out, int out_size) {
    const float* x    = (const float*)d_in[0];
    const float* Wih  = (const float*)d_in[1];
    const float* Whh  = (const float*)d_in[2];
    const float* bih  = (const float*)d_in[3];
    const float* bhh  = (const float*)d_in[4];
    const float* Wmlp = (const float*)d_in[5];
    const float* bmlp = (const float*)d_in[6];
    float* out = (float*)d_out;

    k_init<<<512, 256>>>();
    k_convert<<<4096, 256>>>(Wih, Whh, bih, bhh);
    k_transpose<<<dim3(Tt / 32, Dd / 32, Bb), dim3(32, 8)>>>(x);

    cudaFuncSetAttribute(k_gemm1, cudaFuncAttributeMaxDynamicSharedMemorySize, G1_SMEM);
    k_gemm1<<<dim3(G4 / 128, Mm / 128), 256, G1_SMEM>>>();   // n fastest

    cudaFuncSetAttribute(k_lstm, cudaFuncAttributeMaxDynamicSharedMemorySize, DSMEM_BYTES);
    k_lstm<<<128, 256, DSMEM_BYTES>>>(Wmlp);

    k_out<<<Tt, Bb>>>(bmlp, out);
}

// round 10
// speedup vs baseline: 1.1650x; 1.0157x over previous
#include <cuda_runtime.h>
#include <cuda_bf16.h>
#include <mma.h>

using namespace nvcuda;

#define Bb 256
#define Dd 256
#define Tt 512
#define Hh 512
#define G4 2048
#define Mm (Tt*Bb)   // 131072

// ---------------- device scratch (no runtime allocation allowed) ----------------
__device__ __nv_bfloat16 g_xb[(size_t)Mm*Dd];        // xs as bf16, [t*B+b][d]
__device__ float         g_xg[(size_t)Mm*G4];        // x_gates fp32 (includes biases)
__device__ __nv_bfloat16 g_wih[(size_t)Dd*G4];       // W_ih^T bf16 [k][n]
__device__ __nv_bfloat16 g_whh[(size_t)Hh*G4];       // W_hh^T bf16 [k][n]
__device__ float         g_biasmat[16*G4];           // 16 identical rows of (b_ih+b_hh)
__device__ __nv_bfloat16 g_h[2][(size_t)Bb*Hh];      // double-buffered hidden state
__device__ float         g_plog[16*(size_t)Tt*Bb];   // partial logits per u-tile
__device__ unsigned int  g_ctr[8][32];               // per batch-group counter (128B apart)

__device__ __forceinline__ float tanh_fast(float x) {
    float y; asm("tanh.approx.f32 %0, %1;" : "=f"(y) : "f"(x)); return y;
}
__device__ __forceinline__ float sigm(float x) { return 1.0f / (1.0f + __expf(-x)); }

__device__ __forceinline__ void cp16(void* dst, const void* src) {
    unsigned d = (unsigned)__cvta_generic_to_shared(dst);
    asm volatile("cp.async.cg.shared.global [%0], [%1], 16;" :: "r"(d), "l"(src));
}

// ---------------- init: zero h0 and counters ----------------
__global__ void k_init() {
    int i = blockIdx.x * blockDim.x + threadIdx.x;
    if (i < 8 * 32) ((unsigned*)g_ctr)[i] = 0u;
    if (i < Bb * Hh) g_h[0][i] = __float2bfloat16(0.0f);
}

// ---------------- weight converts (transpose to [k][n], bf16) ----------------
__global__ void k_convert(const float* __restrict__ Wih, const float* __restrict__ Whh,
                          const float* __restrict__ bih, const float* __restrict__ bhh) {
    int i = blockIdx.x * blockDim.x + threadIdx.x;
    if (i < Dd * G4) {
        int k = i / G4, n = i % G4;
        g_wih[i] = __float2bfloat16(Wih[(size_t)n * Dd + k]);
    }
    if (i < Hh * G4) {
        int k = i / G4, n = i % G4;
        g_whh[i] = __float2bfloat16(Whh[(size_t)n * Hh + k]);
    }
    if (i < 16 * G4) {
        int n = i % G4;
        g_biasmat[i] = bih[n] + bhh[n];
    }
}

// ---------------- transpose x (B,D,T) -> g_xb[(t*B+b)*D + d] bf16 ----------------
__global__ void k_transpose(const float* __restrict__ x) {
    __shared__ float tile[32][33];
    int b  = blockIdx.z;
    int d0 = blockIdx.y * 32, t0 = blockIdx.x * 32;
    int tx = threadIdx.x, ty = threadIdx.y;   // 32 x 8
    const float* src = x + ((size_t)b * Dd + d0) * Tt + t0;
    for (int r = ty; r < 32; r += 8)
        tile[r][tx] = src[(size_t)r * Tt + tx];
    __syncthreads();
    for (int r = ty; r < 32; r += 8)
        g_xb[((size_t)(t0 + r) * Bb + b) * Dd + d0 + tx] = __float2bfloat16(tile[tx][r]);
}

// ---------------- GEMM1: 128x128 tile, 256 threads, 3-stage cp.async pipeline ----------------
#define GA_LD 72
#define GB_LD 136
#define G1_STG 3
#define G1_STAGE_B (128*GA_LD*2 + 64*GB_LD*2)
#define G1_SMEM (G1_STG*G1_STAGE_B)

__global__ void __launch_bounds__(256, 2) k_gemm1() {
    extern __shared__ char smg[];
    int n0 = blockIdx.x * 128, m0 = blockIdx.y * 128;   // n fastest -> A-tile reuse in L2
    int tid = threadIdx.x;
    int w = tid >> 5;
    int mw = (w >> 1) * 32, nw = (w & 1) * 64;

    auto As = [&](int s) { return (__nv_bfloat16(*)[GA_LD])(smg + s * G1_STAGE_B); };
    auto Bsx = [&](int s) { return (__nv_bfloat16(*)[GB_LD])(smg + s * G1_STAGE_B + 128 * GA_LD * 2); };

    auto load_stage = [&](int c, int s) {
        int k0 = c * 64;
        __nv_bfloat16 (*A)[GA_LD] = As(s);
        __nv_bfloat16 (*B)[GB_LD] = Bsx(s);
        #pragma unroll
        for (int p = 0; p < 4; p++) {
            int idx = tid + p * 256;
            int r = idx >> 3, cc = (idx & 7) * 8;
            cp16(&A[r][cc], &g_xb[(size_t)(m0 + r) * Dd + k0 + cc]);
        }
        #pragma unroll
        for (int p = 0; p < 4; p++) {
            int idx = tid + p * 256;
            int r = idx >> 4, cc = (idx & 15) * 8;
            cp16(&B[r][cc], &g_wih[(size_t)(k0 + r) * G4 + n0 + cc]);
        }
        asm volatile("cp.async.commit_group;" ::: "memory");
    };

    load_stage(0, 0);
    load_stage(1, 1);

    wmma::fragment<wmma::accumulator, 16, 16, 16, float> acc[2][4];
    #pragma unroll
    for (int i = 0; i < 2; i++)
        #pragma unroll
        for (int j = 0; j < 4; j++)
            wmma::load_matrix_sync(acc[i][j], &g_biasmat[n0 + nw + 16 * j], G4, wmma::mem_row_major);

    #pragma unroll
    for (int c = 0; c < 4; c++) {
        if (c < 2) asm volatile("cp.async.wait_group 1;" ::: "memory");
        else       asm volatile("cp.async.wait_group 0;" ::: "memory");
        __syncthreads();
        int s = c % G1_STG;
        __nv_bfloat16 (*A)[GA_LD] = As(s);
        __nv_bfloat16 (*B)[GB_LD] = Bsx(s);
        #pragma unroll
        for (int kk = 0; kk < 64; kk += 16) {
            wmma::fragment<wmma::matrix_a, 16, 16, 16, __nv_bfloat16, wmma::row_major> af[2];
            wmma::fragment<wmma::matrix_b, 16, 16, 16, __nv_bfloat16, wmma::row_major> bf[4];
            #pragma unroll
            for (int i = 0; i < 2; i++)
                wmma::load_matrix_sync(af[i], &A[mw + 16 * i][kk], GA_LD);
            #pragma unroll
            for (int j = 0; j < 4; j++)
                wmma::load_matrix_sync(bf[j], &B[kk][nw + 16 * j], GB_LD);
            #pragma unroll
            for (int i = 0; i < 2; i++)
                #pragma unroll
                for (int j = 0; j < 4; j++)
                    wmma::mma_sync(acc[i][j], af[i], bf[j], acc[i][j]);
        }
        __syncthreads();
        if (c + 2 < 4) load_stage(c + 2, (c + 2) % G1_STG);
    }
    #pragma unroll
    for (int i = 0; i < 2; i++)
        #pragma unroll
        for (int j = 0; j < 4; j++)
            wmma::store_matrix_sync(&g_xg[(size_t)(m0 + mw + 16 * i) * G4 + n0 + nw + 16 * j],
                                    acc[i][j], G4, wmma::mem_row_major);
}

// ---------------- persistent LSTM recurrence ----------------
// grid = 128 CTAs: blockIdx = bt*16 + ut ; CTA owns batch rows [bt*32,+32), units [ut*32,+32)
// 8 warps: warp w -> batch half (w&1), gate (w>>1). Split-K (4 chains) + SW-pipelined k-loop.
#define BS_LD 136
#define AS_LD 520
#define GT_LD 132
#define DSMEM_BYTES (512*BS_LD*2 + 32*AS_LD*2 + 32*GT_LD*4)

__global__ void __launch_bounds__(256, 1) k_lstm(const float* __restrict__ Wmlp) {
    extern __shared__ char smem[];
    __nv_bfloat16* Bs = (__nv_bfloat16*)smem;                          // [512][BS_LD]
    __nv_bfloat16* As = (__nv_bfloat16*)(smem + 512 * BS_LD * 2);      // [32][AS_LD]
    float*         Gt = (float*)(smem + 512 * BS_LD * 2 + 32 * AS_LD * 2); // [32][GT_LD]
    __shared__ float Wm[32];

    int tid = threadIdx.x, w = tid >> 5;
    int ut = blockIdx.x & 15, bt = blockIdx.x >> 4;
    int u0 = ut * 32, b0 = bt * 32;
    int bh = (w & 1) * 16;        // batch half
    int cg = w >> 1;              // gate index 0..3 (32 gate-cols)
    unsigned* ctr = &g_ctr[bt][0];

    // preload W_hh slice into SMEM: Bs[k][g*32+uu] = W_hh[g*512+u0+uu][k]
    for (int idx = tid; idx < 512 * 16; idx += 256) {
        int k = idx >> 4;
        int col = (idx & 15) * 8;
        int g = col >> 5, uu = col & 31;
        *(uint4*)&Bs[k * BS_LD + col] = *(const uint4*)&g_whh[(size_t)k * G4 + g * 512 + u0 + uu];
    }
    if (tid < 32) Wm[tid] = Wmlp[u0 + tid];

    // elementwise ownership: batch row eb = tid>>3 (0..31), unit quad eq = tid&7 (4 units each)
    int eb = tid >> 3, eq = tid & 7;

    float c_reg[4];
    #pragma unroll
    for (int e = 0; e < 4; e++) c_reg[e] = 0.0f;

    // prefetch xg for t=0 into registers (4 gates x 4 floats)
    float4 xr[4];
    {
        const float* xbase = g_xg + ((size_t)0 * Bb + b0 + eb) * G4 + u0 + eq * 4;
        #pragma unroll
        for (int g = 0; g < 4; g++)
            xr[g] = __ldg((const float4*)(xbase + g * 512));
    }

    __syncthreads();

    for (int t = 0; t < Tt; t++) {
        int cur = t & 1, nxt = cur ^ 1;

        // copy my h rows (32 x 512 bf16) from global (L2-coherent) into SMEM
        const __nv_bfloat16* hsrc = g_h[cur] + (size_t)b0 * Hh;
        #pragma unroll
        for (int it = 0; it < 8; it++) {
            int idx = tid + it * 256;
            int r = idx >> 6, c = (idx & 63) * 8;
            *(uint4*)&As[r * AS_LD + c] = __ldcg((const uint4*)&hsrc[(size_t)r * Hh + c]);
        }
        __syncthreads();

        // MMA: 4 independent chains/warp, explicit double-buffered fragment pipeline
        wmma::fragment<wmma::accumulator, 16, 16, 16, float> acc[2][2];
        #pragma unroll
        for (int j = 0; j < 2; j++)
            #pragma unroll
            for (int p = 0; p < 2; p++)
                wmma::fill_fragment(acc[j][p], 0.0f);

        wmma::fragment<wmma::matrix_a, 16, 16, 16, __nv_bfloat16, wmma::row_major> af[2][2];
        wmma::fragment<wmma::matrix_b, 16, 16, 16, __nv_bfloat16, wmma::row_major> bf[2][2][2];

        // preload chunk 0
        #pragma unroll
        for (int p = 0; p < 2; p++) {
            wmma::load_matrix_sync(af[0][p], &As[bh * AS_LD + p * 16], AS_LD);
            #pragma unroll
            for (int j = 0; j < 2; j++)
                wmma::load_matrix_sync(bf[0][j][p], &Bs[(p * 16) * BS_LD + cg * 32 + 16 * j], BS_LD);
        }

        #pragma unroll
        for (int kc = 0; kc < 16; kc++) {
            int cb = kc & 1, nb = cb ^ 1;
            if (kc < 15) {
                int kn = (kc + 1) * 32;
                #pragma unroll
                for (int p = 0; p < 2; p++) {
                    wmma::load_matrix_sync(af[nb][p], &As[bh * AS_LD + kn + p * 16], AS_LD);
                    #pragma unroll
                    for (int j = 0; j < 2; j++)
                        wmma::load_matrix_sync(bf[nb][j][p], &Bs[(kn + p * 16) * BS_LD + cg * 32 + 16 * j], BS_LD);
                }
            }
            #pragma unroll
            for (int j = 0; j < 2; j++)
                #pragma unroll
                for (int p = 0; p < 2; p++)
                    wmma::mma_sync(acc[j][p], af[cb][p], bf[cb][j][p], acc[j][p]);
        }

        // combine k-parity chains (identical fragment layouts) and store
        #pragma unroll
        for (int j = 0; j < 2; j++) {
            #pragma unroll
            for (int e = 0; e < acc[j][0].num_elements; e++)
                acc[j][0].x[e] += acc[j][1].x[e];
            wmma::store_matrix_sync(&Gt[bh * GT_LD + cg * 32 + 16 * j], acc[j][0], GT_LD, wmma::mem_row_major);
        }

        // xg prefetch for t+1: issue EARLY, before the elementwise sync, so it never
        // delays the arrive below (registers consumed only next step)
        float4 xn[4];
        if (t + 1 < Tt) {
            const float* xbase = g_xg + ((size_t)(t + 1) * Bb + b0 + eb) * G4 + u0 + eq * 4;
            #pragma unroll
            for (int g = 0; g < 4; g++)
                xn[g] = __ldg((const float4*)(xbase + g * 512));
        }
        __syncthreads();

        // elementwise cell: gates = Gt + xr (prefetched); write h + partial logit
        {
            const float* grow = &Gt[eb * GT_LD + eq * 4];
            const float* xf = (const float*)xr;
            __nv_bfloat16 tmp[4];
            float s = 0.0f;
            #pragma unroll
            for (int e = 0; e < 4; e++) {
                float gi = grow[0 * 32 + e] + xf[0 * 4 + e];
                float gf = grow[1 * 32 + e] + xf[1 * 4 + e];
                float gg = grow[2 * 32 + e] + xf[2 * 4 + e];
                float go = grow[3 * 32 + e] + xf[3 * 4 + e];
                float ig = sigm(gi);
                float fg = sigm(gf);
                float gv = tanh_fast(gg);
                float og = sigm(go);
                float cn = fg * c_reg[e] + ig * gv;
                c_reg[e] = cn;
                float hv = og * tanh_fast(cn);
                tmp[e] = __float2bfloat16(hv);
                s += hv * Wm[eq * 4 + e];
            }
            __stcg((uint2*)&g_h[nxt][(size_t)(b0 + eb) * Hh + u0 + eq * 4], *(uint2*)tmp);
            s += __shfl_down_sync(0xffffffffu, s, 4, 8);
            s += __shfl_down_sync(0xffffffffu, s, 2, 8);
            s += __shfl_down_sync(0xffffffffu, s, 1, 8);
            if (eq == 0) g_plog[((size_t)ut * Tt + t) * Bb + b0 + eb] = s;
        }
        #pragma unroll
        for (int g = 0; g < 4; g++) xr[g] = xn[g];

        // group barrier: 16 CTAs of this batch group (skip after last step)
        if (t + 1 < Tt) {
            __syncthreads();
            if (tid == 0) {
                asm volatile("red.release.gpu.global.add.u32 [%0], 1;" :: "l"(ctr) : "memory");
                unsigned tgt = 16u * (unsigned)(t + 1);
                unsigned v;
                do {
                    asm volatile("ld.acquire.gpu.global.u32 %0, [%1];" : "=r"(v) : "l"(ctr) : "memory");
                } while (v < tgt);
            }
            __syncthreads();
        }
    }
}

// ---------------- reduce partial logits -> sigmoid -> out (B, T) ----------------
__global__ void k_out(const float* __restrict__ bmlp, float* __restrict__ out) {
    int t = blockIdx.x, b = threadIdx.x;
    float s = bmlp[0];
    #pragma unroll
    for (int j = 0; j < 16; j++)
        s += g_plog[((size_t)j * Tt + t) * Bb + b];
    out[(size_t)b * Tt + t] = 1.0f / (1.0f + __expf(-s));
}

// ---------------- launch ----------------
extern "C" void kernel_launch(void* const* d_in, const int* in_sizes, int n_in,
                              void* d_out, int out_size) {
    const float* x    = (const float*)d_in[0];
    const float* Wih  = (const float*)d_in[1];
    const float* Whh  = (const float*)d_in[2];
    const float* bih  = (const float*)d_in[3];
    const float* bhh  = (const float*)d_in[4];
    const float* Wmlp = (const float*)d_in[5];
    const float* bmlp = (const float*)d_in[6];
    float* out = (float*)d_out;

    k_init<<<512, 256>>>();
    k_convert<<<4096, 256>>>(Wih, Whh, bih, bhh);
    k_transpose<<<dim3(Tt / 32, Dd / 32, Bb), dim3(32, 8)>>>(x);

    cudaFuncSetAttribute(k_gemm1, cudaFuncAttributeMaxDynamicSharedMemorySize, G1_SMEM);
    k_gemm1<<<dim3(G4 / 128, Mm / 128), 256, G1_SMEM>>>();   // n fastest

    cudaFuncSetAttribute(k_lstm, cudaFuncAttributeMaxDynamicSharedMemorySize, DSMEM_BYTES);
    k_lstm<<<128, 256, DSMEM_BYTES>>>(Wmlp);

    k_out<<<Tt, Bb>>>(bmlp, out);
}

// round 11
// speedup vs baseline: 1.3923x; 1.1952x over previous
#include <cuda_runtime.h>
#include <cuda_bf16.h>
#include <mma.h>
#include <cstdint>

using namespace nvcuda;

#define Bb 256
#define Dd 256
#define Tt 512
#define Hh 512
#define G4 2048
#define Mm (Tt*Bb)   // 131072

// ---------------- device scratch (no runtime allocation allowed) ----------------
__device__ __nv_bfloat16 g_xb[(size_t)Mm*Dd];        // xs as bf16, [t*B+b][d]
__device__ float         g_xg[(size_t)Mm*G4];        // x_gates fp32 (includes biases)
__device__ __nv_bfloat16 g_wih[(size_t)Dd*G4];       // W_ih^T bf16 [k][n]
__device__ __nv_bfloat16 g_whh[(size_t)Hh*G4];       // W_hh^T bf16 [k][n]
__device__ float         g_biasmat[16*G4];           // 16 identical rows of (b_ih+b_hh)
__device__ __nv_bfloat16 g_h[2][(size_t)Bb*Hh];      // double-buffered hidden state
__device__ float         g_plog[64*(size_t)Tt*Bb];   // partial logits per (ut,octet)
__device__ unsigned int  g_ctr[8][32];               // per batch-group counter (128B apart)

__device__ __forceinline__ float tanh_fast(float x) {
    float y; asm("tanh.approx.f32 %0, %1;" : "=f"(y) : "f"(x)); return y;
}
__device__ __forceinline__ float sigm(float x) { return 1.0f / (1.0f + __expf(-x)); }

__device__ __forceinline__ void cp16(void* dst, const void* src) {
    unsigned d = (unsigned)__cvta_generic_to_shared(dst);
    asm volatile("cp.async.cg.shared.global [%0], [%1], 16;" :: "r"(d), "l"(src));
}

__device__ __forceinline__ void ldsm_x4(uint32_t& r0, uint32_t& r1, uint32_t& r2, uint32_t& r3, uint32_t a) {
    asm volatile("ldmatrix.sync.aligned.m8n8.x4.shared.b16 {%0,%1,%2,%3}, [%4];"
                 : "=r"(r0), "=r"(r1), "=r"(r2), "=r"(r3) : "r"(a));
}
__device__ __forceinline__ void ldsm_x4t(uint32_t& r0, uint32_t& r1, uint32_t& r2, uint32_t& r3, uint32_t a) {
    asm volatile("ldmatrix.sync.aligned.m8n8.x4.trans.shared.b16 {%0,%1,%2,%3}, [%4];"
                 : "=r"(r0), "=r"(r1), "=r"(r2), "=r"(r3) : "r"(a));
}
__device__ __forceinline__ void mma16816(float* c, uint32_t a0, uint32_t a1, uint32_t a2, uint32_t a3,
                                         uint32_t b0, uint32_t b1) {
    asm volatile("mma.sync.aligned.m16n8k16.row.col.f32.bf16.bf16.f32 "
                 "{%0,%1,%2,%3},{%4,%5,%6,%7},{%8,%9},{%0,%1,%2,%3};"
                 : "+f"(c[0]), "+f"(c[1]), "+f"(c[2]), "+f"(c[3])
                 : "r"(a0), "r"(a1), "r"(a2), "r"(a3), "r"(b0), "r"(b1));
}

// ---------------- init: zero h0 and counters ----------------
__global__ void k_init() {
    int i = blockIdx.x * blockDim.x + threadIdx.x;
    if (i < 8 * 32) ((unsigned*)g_ctr)[i] = 0u;
    if (i < Bb * Hh) g_h[0][i] = __float2bfloat16(0.0f);
}

// ---------------- weight converts (transpose to [k][n], bf16) ----------------
__global__ void k_convert(const float* __restrict__ Wih, const float* __restrict__ Whh,
                          const float* __restrict__ bih, const float* __restrict__ bhh) {
    int i = blockIdx.x * blockDim.x + threadIdx.x;
    if (i < Dd * G4) {
        int k = i / G4, n = i % G4;
        g_wih[i] = __float2bfloat16(Wih[(size_t)n * Dd + k]);
    }
    if (i < Hh * G4) {
        int k = i / G4, n = i % G4;
        g_whh[i] = __float2bfloat16(Whh[(size_t)n * Hh + k]);
    }
    if (i < 16 * G4) {
        int n = i % G4;
        g_biasmat[i] = bih[n] + bhh[n];
    }
}

// ---------------- transpose x (B,D,T) -> g_xb[(t*B+b)*D + d] bf16 ----------------
__global__ void k_transpose(const float* __restrict__ x) {
    __shared__ float tile[32][33];
    int b  = blockIdx.z;
    int d0 = blockIdx.y * 32, t0 = blockIdx.x * 32;
    int tx = threadIdx.x, ty = threadIdx.y;   // 32 x 8
    const float* src = x + ((size_t)b * Dd + d0) * Tt + t0;
    for (int r = ty; r < 32; r += 8)
        tile[r][tx] = src[(size_t)r * Tt + tx];
    __syncthreads();
    for (int r = ty; r < 32; r += 8)
        g_xb[((size_t)(t0 + r) * Bb + b) * Dd + d0 + tx] = __float2bfloat16(tile[tx][r]);
}

// ---------------- GEMM1 (R9 version, 667us): 128x128 tile, 2-stage cp.async ----------------
#define GA_LD 72
#define GB_LD 136
#define G1_SMEM (2*128*GA_LD*2 + 2*64*GB_LD*2)

__global__ void __launch_bounds__(256, 2) k_gemm1() {
    extern __shared__ char smg[];
    __nv_bfloat16 (*As)[128][GA_LD] = (__nv_bfloat16(*)[128][GA_LD])smg;
    __nv_bfloat16 (*Bs)[64][GB_LD]  = (__nv_bfloat16(*)[64][GB_LD])(smg + 2*128*GA_LD*2);

    int n0 = blockIdx.x * 128, m0 = blockIdx.y * 128;   // n fastest -> A-tile reuse in L2
    int tid = threadIdx.x;
    int w = tid >> 5;
    int mw = (w >> 1) * 32, nw = (w & 1) * 64;

    auto load_stage = [&](int c, int s) {
        int k0 = c * 64;
        #pragma unroll
        for (int p = 0; p < 4; p++) {
            int idx = tid + p * 256;
            int r = idx >> 3, cc = (idx & 7) * 8;
            cp16(&As[s][r][cc], &g_xb[(size_t)(m0 + r) * Dd + k0 + cc]);
        }
        #pragma unroll
        for (int p = 0; p < 4; p++) {
            int idx = tid + p * 256;
            int r = idx >> 4, cc = (idx & 15) * 8;
            cp16(&Bs[s][r][cc], &g_wih[(size_t)(k0 + r) * G4 + n0 + cc]);
        }
        asm volatile("cp.async.commit_group;" ::: "memory");
    };

    load_stage(0, 0);

    wmma::fragment<wmma::accumulator, 16, 16, 16, float> acc[2][4];
    #pragma unroll
    for (int i = 0; i < 2; i++)
        #pragma unroll
        for (int j = 0; j < 4; j++)
            wmma::load_matrix_sync(acc[i][j], &g_biasmat[n0 + nw + 16 * j], G4, wmma::mem_row_major);

    #pragma unroll
    for (int c = 0; c < 4; c++) {
        if (c < 3) load_stage(c + 1, (c + 1) & 1);
        if (c < 3) asm volatile("cp.async.wait_group 1;" ::: "memory");
        else       asm volatile("cp.async.wait_group 0;" ::: "memory");
        __syncthreads();
        int s = c & 1;
        #pragma unroll
        for (int kk = 0; kk < 64; kk += 16) {
            wmma::fragment<wmma::matrix_a, 16, 16, 16, __nv_bfloat16, wmma::row_major> af[2];
            wmma::fragment<wmma::matrix_b, 16, 16, 16, __nv_bfloat16, wmma::row_major> bf[4];
            #pragma unroll
            for (int i = 0; i < 2; i++)
                wmma::load_matrix_sync(af[i], &As[s][mw + 16 * i][kk], GA_LD);
            #pragma unroll
            for (int j = 0; j < 4; j++)
                wmma::load_matrix_sync(bf[j], &Bs[s][kk][nw + 16 * j], GB_LD);
            #pragma unroll
            for (int i = 0; i < 2; i++)
                #pragma unroll
                for (int j = 0; j < 4; j++)
                    wmma::mma_sync(acc[i][j], af[i], bf[j], acc[i][j]);
        }
        __syncthreads();
    }
    #pragma unroll
    for (int i = 0; i < 2; i++)
        #pragma unroll
        for (int j = 0; j < 4; j++)
            wmma::store_matrix_sync(&g_xg[(size_t)(m0 + mw + 16 * i) * G4 + n0 + nw + 16 * j],
                                    acc[i][j], G4, wmma::mem_row_major);
}

// ---------------- persistent LSTM recurrence: register-resident cell ----------------
// 128 CTAs = bt(0..7) x ut(0..15). Warp w: batch-half (w&1), unit-octet uo=(w>>1).
// Raw mma.m16n8k16: warp computes 4 gate-tiles (16 batch x 8 units each); all 4 gates
// of a cell land in one thread's registers -> no Gt SMEM round trip.
#define BS_LD 136
#define AS_LD 520
#define DSMEM_BYTES (512*BS_LD*2 + 32*AS_LD*2)

__global__ void __launch_bounds__(256, 1) k_lstm(const float* __restrict__ Wmlp) {
    extern __shared__ char smem[];
    __nv_bfloat16* Bs = (__nv_bfloat16*)smem;                          // [512][BS_LD]
    __nv_bfloat16* As = (__nv_bfloat16*)(smem + 512 * BS_LD * 2);      // [32][AS_LD]

    int tid = threadIdx.x, w = tid >> 5, lane = tid & 31;
    int ut = blockIdx.x & 15, bt = blockIdx.x >> 4;
    int u0 = ut * 32, b0 = bt * 32;
    int bh = (w & 1);             // batch half (16 rows)
    int uo = w >> 1;              // unit octet 0..3
    unsigned* ctr = &g_ctr[bt][0];

    // preload W_hh slice into SMEM: Bs[k][g*32+uu] = W_hh[g*512+u0+uu][k]
    for (int idx = tid; idx < 512 * 16; idx += 256) {
        int k = idx >> 4;
        int col = (idx & 15) * 8;
        int g = col >> 5, uu = col & 31;
        *(uint4*)&Bs[k * BS_LD + col] = *(const uint4*)&g_whh[(size_t)k * G4 + g * 512 + u0 + uu];
    }

    // ldmatrix addressing
    int grp = lane >> 3, rin = lane & 7;
    uint32_t As_u = (uint32_t)__cvta_generic_to_shared(As);
    uint32_t Bs_u = (uint32_t)__cvta_generic_to_shared(Bs);
    uint32_t aBase = As_u + (uint32_t)(((bh * 16 + (grp & 1) * 8 + rin) * AS_LD + (grp >> 1) * 8) * 2);
    int bRow = (grp & 1) * 8 + rin;
    int gsel = grp >> 1;          // 0/1
    uint32_t bBase01 = Bs_u + (uint32_t)((bRow * BS_LD + (gsel * 32 + uo * 8)) * 2);
    uint32_t bBase23 = Bs_u + (uint32_t)((bRow * BS_LD + ((2 + gsel) * 32 + uo * 8)) * 2);

    // cell ownership (m16n8 D fragment layout): rows {r_lo, r_lo+8}, cols {u_a, u_a+1}
    int r_lo = bh * 16 + (lane >> 2);
    int r_hi = r_lo + 8;
    int u_a  = uo * 8 + (lane & 3) * 2;
    float2 wm = __ldg((const float2*)&Wmlp[u0 + u_a]);

    float c_reg[4] = {0.f, 0.f, 0.f, 0.f};

    // xg prefetch for t=0: per gate, float2 at (row, col u0+g*512+u_a), both rows
    float2 xlo[4], xhi[4];
    {
        const float* plo = g_xg + ((size_t)0 * Bb + b0 + r_lo) * G4 + u0 + u_a;
        const float* phi = g_xg + ((size_t)0 * Bb + b0 + r_hi) * G4 + u0 + u_a;
        #pragma unroll
        for (int g = 0; g < 4; g++) {
            xlo[g] = __ldg((const float2*)(plo + g * 512));
            xhi[g] = __ldg((const float2*)(phi + g * 512));
        }
    }

    __syncthreads();

    for (int t = 0; t < Tt; t++) {
        int cur = t & 1, nxt = cur ^ 1;

        // load h (32 x 512 bf16) from L2 into As
        const __nv_bfloat16* hsrc = g_h[cur] + (size_t)b0 * Hh;
        #pragma unroll
        for (int it = 0; it < 8; it++) {
            int idx = tid + it * 256;
            int r = idx >> 6, c = (idx & 63) * 8;
            *(uint4*)&As[r * AS_LD + c] = __ldcg((const uint4*)&hsrc[(size_t)r * Hh + c]);
        }
        __syncthreads();

        // MMA: acc[gate][k-parity][4elem] -> 8 independent chains of 16
        float acc[4][2][4];
        #pragma unroll
        for (int g = 0; g < 4; g++)
            #pragma unroll
            for (int p = 0; p < 2; p++)
                #pragma unroll
                for (int e = 0; e < 4; e++) acc[g][p][e] = 0.f;

        #pragma unroll
        for (int kc = 0; kc < 16; kc++) {
            #pragma unroll
            for (int p = 0; p < 2; p++) {
                int koff = kc * 32 + p * 16;
                uint32_t a0, a1, a2, a3, q0, q1, q2, q3, s0, s1, s2, s3;
                ldsm_x4 (a0, a1, a2, a3, aBase   + (uint32_t)(koff * 2));
                ldsm_x4t(q0, q1, q2, q3, bBase01 + (uint32_t)(koff * BS_LD * 2));
                ldsm_x4t(s0, s1, s2, s3, bBase23 + (uint32_t)(koff * BS_LD * 2));
                mma16816(acc[0][p], a0, a1, a2, a3, q0, q1);
                mma16816(acc[1][p], a0, a1, a2, a3, q2, q3);
                mma16816(acc[2][p], a0, a1, a2, a3, s0, s1);
                mma16816(acc[3][p], a0, a1, a2, a3, s2, s3);
            }
        }

        // combine k-parity chains
        float gv0[4], gv1[4], gv2[4], gv3[4];
        #pragma unroll
        for (int e = 0; e < 4; e++) {
            gv0[e] = acc[0][0][e] + acc[0][1][e];
            gv1[e] = acc[1][0][e] + acc[1][1][e];
            gv2[e] = acc[2][0][e] + acc[2][1][e];
            gv3[e] = acc[3][0][e] + acc[3][1][e];
        }

        // cell (registers only): e = {lo/ua, lo/ub, hi/ua, hi/ub}
        float xv0[4] = {xlo[0].x, xlo[0].y, xhi[0].x, xhi[0].y};
        float xv1[4] = {xlo[1].x, xlo[1].y, xhi[1].x, xhi[1].y};
        float xv2[4] = {xlo[2].x, xlo[2].y, xhi[2].x, xhi[2].y};
        float xv3[4] = {xlo[3].x, xlo[3].y, xhi[3].x, xhi[3].y};
        float hv[4];
        #pragma unroll
        for (int e = 0; e < 4; e++) {
            float ig = sigm(gv0[e] + xv0[e]);
            float fg = sigm(gv1[e] + xv1[e]);
            float gg = tanh_fast(gv2[e] + xv2[e]);
            float og = sigm(gv3[e] + xv3[e]);
            float cn = fg * c_reg[e] + ig * gg;
            c_reg[e] = cn;
            hv[e] = og * tanh_fast(cn);
        }

        // write h (bf16x2 per row)
        {
            __nv_bfloat162 lo2 = __floats2bfloat162_rn(hv[0], hv[1]);
            __nv_bfloat162 hi2 = __floats2bfloat162_rn(hv[2], hv[3]);
            __stcg((unsigned*)&g_h[nxt][(size_t)(b0 + r_lo) * Hh + u0 + u_a], *(unsigned*)&lo2);
            __stcg((unsigned*)&g_h[nxt][(size_t)(b0 + r_hi) * Hh + u0 + u_a], *(unsigned*)&hi2);
        }

        // partial logits: reduce over the 4 threads covering this row's octet
        {
            float s_lo = hv[0] * wm.x + hv[1] * wm.y;
            float s_hi = hv[2] * wm.x + hv[3] * wm.y;
            s_lo += __shfl_xor_sync(0xffffffffu, s_lo, 1);
            s_lo += __shfl_xor_sync(0xffffffffu, s_lo, 2);
            s_hi += __shfl_xor_sync(0xffffffffu, s_hi, 1);
            s_hi += __shfl_xor_sync(0xffffffffu, s_hi, 2);
            if ((lane & 3) == 0) {
                int slot = ut * 4 + uo;
                g_plog[((size_t)slot * Tt + t) * Bb + b0 + r_lo] = s_lo;
                g_plog[((size_t)slot * Tt + t) * Bb + b0 + r_hi] = s_hi;
            }
        }

        // xg prefetch for t+1 (in flight across the barrier wait)
        if (t + 1 < Tt) {
            const float* plo = g_xg + ((size_t)(t + 1) * Bb + b0 + r_lo) * G4 + u0 + u_a;
            const float* phi = g_xg + ((size_t)(t + 1) * Bb + b0 + r_hi) * G4 + u0 + u_a;
            #pragma unroll
            for (int g = 0; g < 4; g++) {
                xlo[g] = __ldg((const float2*)(plo + g * 512));
                xhi[g] = __ldg((const float2*)(phi + g * 512));
            }
        }

        // group barrier: 16 CTAs of this batch group (skip after last step)
        if (t + 1 < Tt) {
            __syncthreads();
            if (tid == 0) {
                asm volatile("red.release.gpu.global.add.u32 [%0], 1;" :: "l"(ctr) : "memory");
                unsigned tgt = 16u * (unsigned)(t + 1);
                unsigned v;
                do {
                    asm volatile("ld.acquire.gpu.global.u32 %0, [%1];" : "=r"(v) : "l"(ctr) : "memory");
                } while (v < tgt);
            }
            __syncthreads();
        }
    }
}

// ---------------- reduce partial logits -> sigmoid -> out (B, T) ----------------
__global__ void k_out(const float* __restrict__ bmlp, float* __restrict__ out) {
    int t = blockIdx.x, b = threadIdx.x;
    float s = bmlp[0];
    #pragma unroll
    for (int j = 0; j < 64; j++)
        s += g_plog[((size_t)j * Tt + t) * Bb + b];
    out[(size_t)b * Tt + t] = 1.0f / (1.0f + __expf(-s));
}

// ---------------- launch ----------------
extern "C" void kernel_launch(void* const* d_in, const int* in_sizes, int n_in,
                              void* d_out, int out_size) {
    const float* x    = (const float*)d_in[0];
    const float* Wih  = (const float*)d_in[1];
    const float* Whh  = (const float*)d_in[2];
    const float* bih  = (const float*)d_in[3];
    const float* bhh  = (const float*)d_in[4];
    const float* Wmlp = (const float*)d_in[5];
    const float* bmlp = (const float*)d_in[6];
    float* out = (float*)d_out;

    k_init<<<512, 256>>>();
    k_convert<<<4096, 256>>>(Wih, Whh, bih, bhh);
    k_transpose<<<dim3(Tt / 32, Dd / 32, Bb), dim3(32, 8)>>>(x);

    cudaFuncSetAttribute(k_gemm1, cudaFuncAttributeMaxDynamicSharedMemorySize, G1_SMEM);
    k_gemm1<<<dim3(G4 / 128, Mm / 128), 256, G1_SMEM>>>();   // n fastest

    cudaFuncSetAttribute(k_lstm, cudaFuncAttributeMaxDynamicSharedMemorySize, DSMEM_BYTES);
    k_lstm<<<128, 256, DSMEM_BYTES>>>(Wmlp);

    k_out<<<Tt, Bb>>>(bmlp, out);
}